// round 12
// baseline (speedup 1.0000x reference)
#include <cuda_runtime.h>
#include <cuda_bf16.h>
#include <cuda_fp16.h>
#include <cstdint>

// Problem constants
constexpr int kB = 2, kS = 2048, kH = 32, kHK = 8, kD = 128;
constexpr int kN  = kB * kS;      // 4096
constexpr int kHD = kH * kD;      // 4096
constexpr int kHKD = kHK * kD;    // 1024
constexpr float kScale = 0.08838834764831845f;           // 1/sqrt(128)
constexpr float kSc2   = kScale * 1.4426950408889634f;   // scale * log2(e)

// Tiling: BM=64 queries/CTA, BN=64 keys/tile, 4 warps, 3 CTAs/SM
constexpr int BM = 64, BN = 64, NT = 128;
constexpr int NQB = kS / BM;      // 32
constexpr int KP = 136;  // fp16 pitch, conflict-free LDSM (+4 banks/row)
constexpr int VP = 72;

// SMEM element offsets (fp16 elements)
constexpr int eK0 = 0;                    // K buf0 [64][136] fp16
constexpr int eK1 = eK0 + BN * KP;        // K buf1 (Q fp32 staging overlays K1+V)
constexpr int eV  = eK1 + BN * KP;        // V [128][72] fp16
constexpr int SMEM_ELEMS = eV + kD * VP;       // 26624
constexpr int SMEM_BYTES = SMEM_ELEMS * 2;     // 53248 -> 3 CTAs/SM (159744 < 227KB)
static_assert(3 * SMEM_BYTES <= 227328, "smem");
// Q fp32 staging overlay at eK1: 64 x 132 floats = 33792 B fits in K1+V (35840 B)
constexpr int QSP = 132;
static_assert(eK1 * 2 + BM * QSP * 4 <= SMEM_BYTES, "overlay");

// fp16 scratch: K in source layout; V transposed [bh][d][s]
__device__ __half g_K16[(size_t)kN * kHKD];
__device__ __half g_Vt [(size_t)kN * kHKD];

// ---------------------------------------------------------------------------
// Prep kernels (3 launches)
// ---------------------------------------------------------------------------
__global__ void cache_copy_kernel(const float* __restrict__ kc, const float* __restrict__ vc,
                                  float* __restrict__ okc, float* __restrict__ ovc) {
    int i = blockIdx.x * blockDim.x + threadIdx.x;
    if (i < kN * kHKD / 4) {
        reinterpret_cast<float4*>(okc)[i] = reinterpret_cast<const float4*>(kc)[i];
        reinterpret_cast<float4*>(ovc)[i] = reinterpret_cast<const float4*>(vc)[i];
    }
}
// scatter K/V into caches + convert K to fp16 (k is read once)
__global__ void scatter_cvt_kernel(const float* __restrict__ k, const float* __restrict__ v,
                                   const int* __restrict__ slot,
                                   float* __restrict__ okc, float* __restrict__ ovc) {
    int i = blockIdx.x * blockDim.x + threadIdx.x;
    constexpr int per_row = kHKD / 4;
    if (i >= kN * per_row) return;
    int n = i / per_row, c = i - n * per_row;
    float4 fk = reinterpret_cast<const float4*>(k)[i];
    reinterpret_cast<__half2*>(g_K16)[2 * i]     = __floats2half2_rn(fk.x, fk.y);
    reinterpret_cast<__half2*>(g_K16)[2 * i + 1] = __floats2half2_rn(fk.z, fk.w);
    int s = slot[n];
    if (s >= 0 && s < kN) {
        reinterpret_cast<float4*>(okc)[s * per_row + c] = fk;
        reinterpret_cast<float4*>(ovc)[s * per_row + c] = reinterpret_cast<const float4*>(v)[i];
    }
}
// V -> transposed fp16  Vt[bh][d][s]
__global__ void vtrans_kernel(const float* __restrict__ v) {
    __shared__ __half th[32][33];
    int bh = blockIdx.z;
    int d0 = blockIdx.y * 32, s0 = blockIdx.x * 32;
    int b = bh >> 3, hk = bh & 7;
    int tx = threadIdx.x, ty = threadIdx.y;
    float x = v[((size_t)(b * kS + s0 + ty) * kHK + hk) * kD + d0 + tx];
    th[ty][tx] = __float2half_rn(x);
    __syncthreads();
    g_Vt[((size_t)(bh * kD + d0 + ty)) * kS + s0 + tx] = th[tx][ty];
}

// ---------------------------------------------------------------------------
// PTX helpers
// ---------------------------------------------------------------------------
__device__ __forceinline__ void mma16816(float* d,
                                         unsigned a0, unsigned a1, unsigned a2, unsigned a3,
                                         unsigned b0, unsigned b1) {
    asm volatile(
        "mma.sync.aligned.m16n8k16.row.col.f32.f16.f16.f32 "
        "{%0,%1,%2,%3},{%4,%5,%6,%7},{%8,%9},{%0,%1,%2,%3};\n"
        : "+f"(d[0]), "+f"(d[1]), "+f"(d[2]), "+f"(d[3])
        : "r"(a0), "r"(a1), "r"(a2), "r"(a3), "r"(b0), "r"(b1));
}
__device__ __forceinline__ void ldsm4(unsigned& r0, unsigned& r1,
                                      unsigned& r2, unsigned& r3, unsigned a) {
    asm volatile("ldmatrix.sync.aligned.m8n8.x4.shared.b16 {%0,%1,%2,%3}, [%4];\n"
                 : "=r"(r0), "=r"(r1), "=r"(r2), "=r"(r3) : "r"(a));
}
__device__ __forceinline__ void cp16(unsigned dst, const void* src) {
    asm volatile("cp.async.cg.shared.global [%0], [%1], 16;\n" :: "r"(dst), "l"(src));
}
__device__ __forceinline__ void cp_commit() {
    asm volatile("cp.async.commit_group;" ::: "memory");
}
__device__ __forceinline__ void cp_wait1() {
    asm volatile("cp.async.wait_group 1;" ::: "memory");
}
__device__ __forceinline__ float ex2(float x) {
    float y;
    asm("ex2.approx.f32 %0, %1;" : "=f"(y) : "f"(x));
    return y;
}
__device__ __forceinline__ unsigned pkh2(float x, float y) {
    __half2 t = __floats2half2_rn(x, y);
    return *reinterpret_cast<unsigned*>(&t);
}

// ---------------------------------------------------------------------------
// Flash attention: pure fp16 MMA, static softmax with immediate fp16 pack,
// double-K single-V pipeline, 3 CTAs/SM.
// Grid (32, 32, 2), 128 threads; warp w owns rows [16w, 16w+16).
// ---------------------------------------------------------------------------
__global__ __launch_bounds__(NT, 3)
void attn_kernel(const float* __restrict__ q, float* __restrict__ o) {
    extern __shared__ __half sm[];
    float* qstage = reinterpret_cast<float*>(sm + eK1);   // overlay on K1+V

    const int tid = threadIdx.x;
    const int w = tid >> 5;
    const int lane = tid & 31;
    const int qd = lane >> 2;   // 0..7
    const int qp = lane & 3;    // 0..3
    const int qb = (NQB - 1) - blockIdx.x;   // heavy CTAs first
    const int h = blockIdx.y, b = blockIdx.z;
    const int hk = h >> 2;
    const int bh = b * kHK + hk;
    const int nk = qb + 1;
    const int arow = w * 16 + qd;           // local row
    const int rg0 = qb * BM + arow;         // global q row
    const int rg1 = rg0 + 8;

    const uint32_t sb = (uint32_t)__cvta_generic_to_shared(sm);

    // ldmatrix per-lane relative offsets
    const int lrow = ((lane >> 4) << 3) + (lane & 7);
    const int lcol = ((lane >> 3) & 1) << 3;
    const unsigned lK = (unsigned)((lrow * KP + lcol) * 2);
    const unsigned lV = (unsigned)((lrow * VP + lcol) * 2);
    const unsigned uK[2] = {sb + eK0 * 2 + lK, sb + eK1 * 2 + lK};
    const unsigned uV = sb + eV * 2 + lV;

    const __half* gK0 = g_K16 + ((size_t)(b * kS)) * kHKD + hk * kD;
    const __half* gV0 = g_Vt + (size_t)bh * kD * kS;

    auto prefetchK = [&](int kt) {
        unsigned dK = sb + ((kt & 1) ? eK1 : eK0) * 2;
        const __half* kp = gK0 + (size_t)kt * BN * kHKD;
        #pragma unroll
        for (int it = 0; it < 8; ++it) {
            int idx = it * NT + tid;            // 0..1023
            int r = idx >> 4, c = (idx & 15) * 8;
            cp16(dK + (unsigned)((r * KP + c) * 2), kp + (size_t)r * kHKD + c);
        }
        cp_commit();
    };
    auto prefetchV = [&](int kt) {
        const __half* vp = gV0 + (size_t)kt * BN;
        #pragma unroll
        for (int it = 0; it < 8; ++it) {
            int idx = it * NT + tid;            // 0..1023
            int r = idx >> 3, c = (idx & 7) * 8;
            cp16(sb + eV * 2 + (unsigned)((r * VP + c) * 2), vp + (size_t)r * kS + c);
        }
        cp_commit();
    };

    prefetchK(0);    // group: K(0)  (K0 region, not under overlay)

    // ---- Q: stage fp32 (pre-scaled) in overlay, hoist fp16 frags ----
    const float* qbase = q + ((size_t)(b * kS + qb * BM)) * kHD + h * kD;
    #pragma unroll
    for (int it = 0; it < 16; ++it) {
        int idx = it * NT + tid;               // 0..2047 float4s
        int r = idx >> 5, c = (idx & 31) * 4;
        float4 f = *reinterpret_cast<const float4*>(qbase + (size_t)r * kHD + c);
        f.x *= kSc2; f.y *= kSc2; f.z *= kSc2; f.w *= kSc2;
        *reinterpret_cast<float4*>(&qstage[r * QSP + c]) = f;
    }
    __syncthreads();

    unsigned ah[8][4];
    #pragma unroll
    for (int c = 0; c < 8; ++c) {
        int k0 = c * 16 + qp * 2;
        #pragma unroll
        for (int e = 0; e < 4; ++e) {
            int rr = (e & 1) ? arow + 8 : arow;
            int cc = k0 + ((e >> 1) << 3);
            float2 f = *reinterpret_cast<const float2*>(&qstage[rr * QSP + cc]);
            ah[c][e] = pkh2(f.x, f.y);
        }
    }
    __syncthreads();   // overlay dead; V region free

    prefetchV(0);      // group: V(0)

    float o_[16][4];
    #pragma unroll
    for (int j = 0; j < 16; ++j)
        #pragma unroll
        for (int e = 0; e < 4; ++e) o_[j][e] = 0.f;
    float lr0 = 0.f, lr1 = 0.f;

    for (int kt = 0; kt < nk; ++kt) {
        const int bw = kt & 1;

        // K(kt) ready (allow V(kt) pending)
        cp_wait1();
        __syncthreads();

        // ---- S = Q16 . K16 ----
        float s_[8][4];
        #pragma unroll
        for (int j = 0; j < 8; ++j)
            #pragma unroll
            for (int e = 0; e < 4; ++e) s_[j][e] = 0.f;

        #pragma unroll
        for (int c = 0; c < 8; ++c) {
            #pragma unroll
            for (int jp = 0; jp < 4; ++jp) {
                unsigned koff = (unsigned)((jp * 16 * KP + c * 16) * 2);
                unsigned b0, b1, b2, b3;
                ldsm4(b0, b1, b2, b3, uK[bw] + koff);
                mma16816(s_[2 * jp],     ah[c][0], ah[c][1], ah[c][2], ah[c][3], b0, b1);
                mma16816(s_[2 * jp + 1], ah[c][0], ah[c][1], ah[c][2], ah[c][3], b2, b3);
            }
        }
        __syncthreads();               // all warps done reading K(kt)
        if (kt + 1 < nk) prefetchK(kt + 1);   // into other K buf

        // ---- static softmax: p = 2^s, pack to fp16 immediately ----
        const bool msk = (kt == qb);
        unsigned pp[8][2];
        #pragma unroll
        for (int j = 0; j < 8; ++j) {
            int cl = kt * BN + j * 8 + qp * 2;
            float p0 = ex2(s_[j][0]);
            float p1 = ex2(s_[j][1]);
            float p2 = ex2(s_[j][2]);
            float p3 = ex2(s_[j][3]);
            if (msk) {
                if (cl     > rg0) p0 = 0.f;
                if (cl + 1 > rg0) p1 = 0.f;
                if (cl     > rg1) p2 = 0.f;
                if (cl + 1 > rg1) p3 = 0.f;
            }
            lr0 += p0 + p1;
            lr1 += p2 + p3;
            pp[j][0] = pkh2(p0, p1);
            pp[j][1] = pkh2(p2, p3);
        }

        // V(kt) ready (allow K(kt+1) pending)
        cp_wait1();
        __syncthreads();

        // ---- O += P16 . V16 ----
        #pragma unroll
        for (int cc = 0; cc < 4; ++cc) {
            unsigned p0 = pp[2 * cc][0];
            unsigned p1 = pp[2 * cc][1];
            unsigned p2 = pp[2 * cc + 1][0];
            unsigned p3 = pp[2 * cc + 1][1];
            #pragma unroll
            for (int jp = 0; jp < 8; ++jp) {
                unsigned voff = (unsigned)((jp * 16 * VP + cc * 16) * 2);
                unsigned b0, b1, b2, b3;
                ldsm4(b0, b1, b2, b3, uV + voff);
                mma16816(o_[2 * jp],     p0, p1, p2, p3, b0, b1);
                mma16816(o_[2 * jp + 1], p0, p1, p2, p3, b2, b3);
            }
        }
        __syncthreads();               // all warps done reading V(kt)
        if (kt + 1 < nk) prefetchV(kt + 1);
    }

    // ---- final l reduce over qp lanes, normalize, store ----
    lr0 += __shfl_xor_sync(0xffffffffu, lr0, 1);
    lr0 += __shfl_xor_sync(0xffffffffu, lr0, 2);
    lr1 += __shfl_xor_sync(0xffffffffu, lr1, 1);
    lr1 += __shfl_xor_sync(0xffffffffu, lr1, 2);
    float inv0 = 1.0f / lr0, inv1 = 1.0f / lr1;
    float* obase = o + ((size_t)(b * kS + qb * BM + w * 16)) * kHD + h * kD;
    #pragma unroll
    for (int j = 0; j < 16; ++j) {
        int dcol = j * 8 + qp * 2;
        float2 r0 = {o_[j][0] * inv0, o_[j][1] * inv0};
        float2 r1 = {o_[j][2] * inv1, o_[j][3] * inv1};
        *reinterpret_cast<float2*>(obase + (size_t)qd * kHD + dcol)       = r0;
        *reinterpret_cast<float2*>(obase + (size_t)(qd + 8) * kHD + dcol) = r1;
    }
}

// ---------------------------------------------------------------------------
// Launch
// ---------------------------------------------------------------------------
extern "C" void kernel_launch(void* const* d_in, const int* in_sizes, int n_in,
                              void* d_out, int out_size) {
    const float* q    = (const float*)d_in[0];
    const float* k    = (const float*)d_in[1];
    const float* v    = (const float*)d_in[2];
    const float* kc   = (const float*)d_in[3];
    const float* vc   = (const float*)d_in[4];
    const int*   slot = (const int*)d_in[5];

    float* out    = (float*)d_out;
    float* out_o  = out;
    float* out_kc = out + (size_t)kN * kHD;
    float* out_vc = out_kc + (size_t)kN * kHKD;

    cudaFuncSetAttribute(attn_kernel,
                         cudaFuncAttributeMaxDynamicSharedMemorySize, SMEM_BYTES);

    int n4 = kN * kHKD / 4;
    cache_copy_kernel<<<(n4 + 255) / 256, 256>>>(kc, vc, out_kc, out_vc);
    scatter_cvt_kernel<<<(n4 + 255) / 256, 256>>>(k, v, slot, out_kc, out_vc);
    dim3 vg(kS / 32, kD / 32, kB * kHK);
    vtrans_kernel<<<vg, dim3(32, 32)>>>(v);

    dim3 grid(NQB, kH, kB);
    attn_kernel<<<grid, NT, SMEM_BYTES>>>(q, out_o);
}

// round 13
// speedup vs baseline: 1.0211x; 1.0211x over previous
#include <cuda_runtime.h>
#include <cuda_bf16.h>
#include <cuda_fp16.h>
#include <cstdint>

// Problem constants
constexpr int kB = 2, kS = 2048, kH = 32, kHK = 8, kD = 128;
constexpr int kN  = kB * kS;      // 4096
constexpr int kHD = kH * kD;      // 4096
constexpr int kHKD = kHK * kD;    // 1024
constexpr float kScale = 0.08838834764831845f;           // 1/sqrt(128)
constexpr float kSc2   = kScale * 1.4426950408889634f;   // scale * log2(e)

// Tiling: BM=64 queries/CTA, BN=64 keys/tile, 4 warps, 2 CTAs/SM
constexpr int BM = 64, BN = 64, NT = 128;
constexpr int NQB = kS / BM;      // 32
constexpr int KP = 136;  // fp16 pitch, conflict-free LDSM (+4 banks/row)
constexpr int VP = 72;

// SMEM element offsets (fp16 elements)
constexpr int eK0 = 0;                    // K buf0 [64][136] fp16
constexpr int eK1 = eK0 + BN * KP;        // K buf1 (Q fp32 staging overlays K1+V)
constexpr int eV  = eK1 + BN * KP;        // V [128][72] fp16
constexpr int SMEM_ELEMS = eV + kD * VP;       // 26624
constexpr int SMEM_BYTES = SMEM_ELEMS * 2;     // 53248 -> 2 CTAs/SM
static_assert(2 * SMEM_BYTES <= 227328, "smem");
// Q fp32 staging overlay at eK1: 64 x 132 floats = 33792 B fits in K1+V (35840 B)
constexpr int QSP = 132;
static_assert(eK1 * 2 + BM * QSP * 4 <= SMEM_BYTES, "overlay");

// fp16 scratch: K in source layout; V transposed [bh][d][s]
__device__ __half g_K16[(size_t)kN * kHKD];
__device__ __half g_Vt [(size_t)kN * kHKD];

// ---------------------------------------------------------------------------
// Prep kernels (3 launches)
// ---------------------------------------------------------------------------
__global__ void cache_copy_kernel(const float* __restrict__ kc, const float* __restrict__ vc,
                                  float* __restrict__ okc, float* __restrict__ ovc) {
    int i = blockIdx.x * blockDim.x + threadIdx.x;
    if (i < kN * kHKD / 4) {
        reinterpret_cast<float4*>(okc)[i] = reinterpret_cast<const float4*>(kc)[i];
        reinterpret_cast<float4*>(ovc)[i] = reinterpret_cast<const float4*>(vc)[i];
    }
}
// scatter K/V into caches + convert K to fp16 (k is read once)
__global__ void scatter_cvt_kernel(const float* __restrict__ k, const float* __restrict__ v,
                                   const int* __restrict__ slot,
                                   float* __restrict__ okc, float* __restrict__ ovc) {
    int i = blockIdx.x * blockDim.x + threadIdx.x;
    constexpr int per_row = kHKD / 4;
    if (i >= kN * per_row) return;
    int n = i / per_row, c = i - n * per_row;
    float4 fk = reinterpret_cast<const float4*>(k)[i];
    reinterpret_cast<__half2*>(g_K16)[2 * i]     = __floats2half2_rn(fk.x, fk.y);
    reinterpret_cast<__half2*>(g_K16)[2 * i + 1] = __floats2half2_rn(fk.z, fk.w);
    int s = slot[n];
    if (s >= 0 && s < kN) {
        reinterpret_cast<float4*>(okc)[s * per_row + c] = fk;
        reinterpret_cast<float4*>(ovc)[s * per_row + c] = reinterpret_cast<const float4*>(v)[i];
    }
}
// V -> transposed fp16  Vt[bh][d][s]
__global__ void vtrans_kernel(const float* __restrict__ v) {
    __shared__ __half th[32][33];
    int bh = blockIdx.z;
    int d0 = blockIdx.y * 32, s0 = blockIdx.x * 32;
    int b = bh >> 3, hk = bh & 7;
    int tx = threadIdx.x, ty = threadIdx.y;
    float x = v[((size_t)(b * kS + s0 + ty) * kHK + hk) * kD + d0 + tx];
    th[ty][tx] = __float2half_rn(x);
    __syncthreads();
    g_Vt[((size_t)(bh * kD + d0 + ty)) * kS + s0 + tx] = th[tx][ty];
}

// ---------------------------------------------------------------------------
// PTX helpers
// ---------------------------------------------------------------------------
__device__ __forceinline__ void mma16816(float* d,
                                         unsigned a0, unsigned a1, unsigned a2, unsigned a3,
                                         unsigned b0, unsigned b1) {
    asm volatile(
        "mma.sync.aligned.m16n8k16.row.col.f32.f16.f16.f32 "
        "{%0,%1,%2,%3},{%4,%5,%6,%7},{%8,%9},{%0,%1,%2,%3};\n"
        : "+f"(d[0]), "+f"(d[1]), "+f"(d[2]), "+f"(d[3])
        : "r"(a0), "r"(a1), "r"(a2), "r"(a3), "r"(b0), "r"(b1));
}
__device__ __forceinline__ void ldsm4(unsigned* r, unsigned a) {
    asm volatile("ldmatrix.sync.aligned.m8n8.x4.shared.b16 {%0,%1,%2,%3}, [%4];\n"
                 : "=r"(r[0]), "=r"(r[1]), "=r"(r[2]), "=r"(r[3]) : "r"(a));
}
__device__ __forceinline__ void cp16(unsigned dst, const void* src) {
    asm volatile("cp.async.cg.shared.global [%0], [%1], 16;\n" :: "r"(dst), "l"(src));
}
__device__ __forceinline__ void cp_commit() {
    asm volatile("cp.async.commit_group;" ::: "memory");
}
__device__ __forceinline__ void cp_wait1() {
    asm volatile("cp.async.wait_group 1;" ::: "memory");
}
__device__ __forceinline__ float ex2(float x) {
    float y;
    asm("ex2.approx.f32 %0, %1;" : "=f"(y) : "f"(x));
    return y;
}
__device__ __forceinline__ unsigned pkh2(float x, float y) {
    __half2 t = __floats2half2_rn(x, y);
    return *reinterpret_cast<unsigned*>(&t);
}

// ---------------------------------------------------------------------------
// Flash attention: pure fp16 MMA, static softmax with immediate fp16 pack,
// double-K single-V cp.async pipeline, depth-2 ldsm software pipeline,
// 2 CTAs/SM. Grid (32, 32, 2), 128 threads; warp w owns rows [16w, 16w+16).
// ---------------------------------------------------------------------------
__global__ __launch_bounds__(NT, 2)
void attn_kernel(const float* __restrict__ q, float* __restrict__ o) {
    extern __shared__ __half sm[];
    float* qstage = reinterpret_cast<float*>(sm + eK1);   // overlay on K1+V

    const int tid = threadIdx.x;
    const int w = tid >> 5;
    const int lane = tid & 31;
    const int qd = lane >> 2;   // 0..7
    const int qp = lane & 3;    // 0..3
    const int qb = (NQB - 1) - blockIdx.x;   // heavy CTAs first
    const int h = blockIdx.y, b = blockIdx.z;
    const int hk = h >> 2;
    const int bh = b * kHK + hk;
    const int nk = qb + 1;
    const int arow = w * 16 + qd;           // local row
    const int rg0 = qb * BM + arow;         // global q row
    const int rg1 = rg0 + 8;

    const uint32_t sb = (uint32_t)__cvta_generic_to_shared(sm);

    // ldmatrix per-lane relative offsets
    const int lrow = ((lane >> 4) << 3) + (lane & 7);
    const int lcol = ((lane >> 3) & 1) << 3;
    const unsigned lK = (unsigned)((lrow * KP + lcol) * 2);
    const unsigned lV = (unsigned)((lrow * VP + lcol) * 2);
    const unsigned uK[2] = {sb + eK0 * 2 + lK, sb + eK1 * 2 + lK};
    const unsigned uV = sb + eV * 2 + lV;

    const __half* gK0 = g_K16 + ((size_t)(b * kS)) * kHKD + hk * kD;
    const __half* gV0 = g_Vt + (size_t)bh * kD * kS;

    auto prefetchK = [&](int kt) {
        unsigned dK = sb + ((kt & 1) ? eK1 : eK0) * 2;
        const __half* kp = gK0 + (size_t)kt * BN * kHKD;
        #pragma unroll
        for (int it = 0; it < 8; ++it) {
            int idx = it * NT + tid;            // 0..1023
            int r = idx >> 4, c = (idx & 15) * 8;
            cp16(dK + (unsigned)((r * KP + c) * 2), kp + (size_t)r * kHKD + c);
        }
        cp_commit();
    };
    auto prefetchV = [&](int kt) {
        const __half* vp = gV0 + (size_t)kt * BN;
        #pragma unroll
        for (int it = 0; it < 8; ++it) {
            int idx = it * NT + tid;            // 0..1023
            int r = idx >> 3, c = (idx & 7) * 8;
            cp16(sb + eV * 2 + (unsigned)((r * VP + c) * 2), vp + (size_t)r * kS + c);
        }
        cp_commit();
    };

    prefetchK(0);    // group: K(0)  (K0 region, not under overlay)

    // ---- Q: stage fp32 (pre-scaled) in overlay, hoist fp16 frags ----
    const float* qbase = q + ((size_t)(b * kS + qb * BM)) * kHD + h * kD;
    #pragma unroll
    for (int it = 0; it < 16; ++it) {
        int idx = it * NT + tid;               // 0..2047 float4s
        int r = idx >> 5, c = (idx & 31) * 4;
        float4 f = *reinterpret_cast<const float4*>(qbase + (size_t)r * kHD + c);
        f.x *= kSc2; f.y *= kSc2; f.z *= kSc2; f.w *= kSc2;
        *reinterpret_cast<float4*>(&qstage[r * QSP + c]) = f;
    }
    __syncthreads();

    unsigned ah[8][4];
    #pragma unroll
    for (int c = 0; c < 8; ++c) {
        int k0 = c * 16 + qp * 2;
        #pragma unroll
        for (int e = 0; e < 4; ++e) {
            int rr = (e & 1) ? arow + 8 : arow;
            int cc = k0 + ((e >> 1) << 3);
            float2 f = *reinterpret_cast<const float2*>(&qstage[rr * QSP + cc]);
            ah[c][e] = pkh2(f.x, f.y);
        }
    }
    __syncthreads();   // overlay dead; V region free

    prefetchV(0);      // group: V(0)

    float o_[16][4];
    #pragma unroll
    for (int j = 0; j < 16; ++j)
        #pragma unroll
        for (int e = 0; e < 4; ++e) o_[j][e] = 0.f;
    float lr0 = 0.f, lr1 = 0.f;

    for (int kt = 0; kt < nk; ++kt) {
        const int bw = kt & 1;

        // K(kt) ready (allow V(kt) pending)
        cp_wait1();
        __syncthreads();

        // ---- S = Q16 . K16 (depth-2 pipelined ldsm ring) ----
        float s_[8][4];
        #pragma unroll
        for (int j = 0; j < 8; ++j)
            #pragma unroll
            for (int e = 0; e < 4; ++e) s_[j][e] = 0.f;

        {
            // idx = c*4 + jp ; addr = ((idx&3)*16*KP + (idx>>2)*16)*2
            unsigned kf[3][4];
            ldsm4(kf[0], uK[bw] + (unsigned)(((0 & 3) * 16 * KP + (0 >> 2) * 16) * 2));
            ldsm4(kf[1], uK[bw] + (unsigned)(((1 & 3) * 16 * KP + (1 >> 2) * 16) * 2));
            #pragma unroll
            for (int idx = 0; idx < 32; ++idx) {
                if (idx + 2 < 32) {
                    int nx = idx + 2;
                    ldsm4(kf[nx % 3],
                          uK[bw] + (unsigned)(((nx & 3) * 16 * KP + (nx >> 2) * 16) * 2));
                }
                const int c = idx >> 2, jp = idx & 3;
                unsigned* f = kf[idx % 3];
                mma16816(s_[2 * jp],     ah[c][0], ah[c][1], ah[c][2], ah[c][3], f[0], f[1]);
                mma16816(s_[2 * jp + 1], ah[c][0], ah[c][1], ah[c][2], ah[c][3], f[2], f[3]);
            }
        }
        __syncthreads();               // all warps done reading K(kt)
        if (kt + 1 < nk) prefetchK(kt + 1);   // into other K buf

        // ---- static softmax: p = 2^s, pack to fp16 immediately ----
        const bool msk = (kt == qb);
        unsigned pp[8][2];
        #pragma unroll
        for (int j = 0; j < 8; ++j) {
            int cl = kt * BN + j * 8 + qp * 2;
            float p0 = ex2(s_[j][0]);
            float p1 = ex2(s_[j][1]);
            float p2 = ex2(s_[j][2]);
            float p3 = ex2(s_[j][3]);
            if (msk) {
                if (cl     > rg0) p0 = 0.f;
                if (cl + 1 > rg0) p1 = 0.f;
                if (cl     > rg1) p2 = 0.f;
                if (cl + 1 > rg1) p3 = 0.f;
            }
            lr0 += p0 + p1;
            lr1 += p2 + p3;
            pp[j][0] = pkh2(p0, p1);
            pp[j][1] = pkh2(p2, p3);
        }

        // V(kt) ready (allow K(kt+1) pending)
        cp_wait1();
        __syncthreads();

        // ---- O += P16 . V16 (depth-2 pipelined ldsm ring) ----
        {
            // idx = cc*8 + jp ; addr = ((idx&7)*16*VP + (idx>>3)*16)*2
            unsigned vf[3][4];
            ldsm4(vf[0], uV + (unsigned)(((0 & 7) * 16 * VP + (0 >> 3) * 16) * 2));
            ldsm4(vf[1], uV + (unsigned)(((1 & 7) * 16 * VP + (1 >> 3) * 16) * 2));
            #pragma unroll
            for (int idx = 0; idx < 32; ++idx) {
                if (idx + 2 < 32) {
                    int nx = idx + 2;
                    ldsm4(vf[nx % 3],
                          uV + (unsigned)(((nx & 7) * 16 * VP + (nx >> 3) * 16) * 2));
                }
                const int cc = idx >> 3, jp = idx & 7;
                unsigned* f = vf[idx % 3];
                mma16816(o_[2 * jp],     pp[2 * cc][0], pp[2 * cc][1],
                         pp[2 * cc + 1][0], pp[2 * cc + 1][1], f[0], f[1]);
                mma16816(o_[2 * jp + 1], pp[2 * cc][0], pp[2 * cc][1],
                         pp[2 * cc + 1][0], pp[2 * cc + 1][1], f[2], f[3]);
            }
        }
        __syncthreads();               // all warps done reading V(kt)
        if (kt + 1 < nk) prefetchV(kt + 1);
    }

    // ---- final l reduce over qp lanes, normalize, store ----
    lr0 += __shfl_xor_sync(0xffffffffu, lr0, 1);
    lr0 += __shfl_xor_sync(0xffffffffu, lr0, 2);
    lr1 += __shfl_xor_sync(0xffffffffu, lr1, 1);
    lr1 += __shfl_xor_sync(0xffffffffu, lr1, 2);
    float inv0 = 1.0f / lr0, inv1 = 1.0f / lr1;
    float* obase = o + ((size_t)(b * kS + qb * BM + w * 16)) * kHD + h * kD;
    #pragma unroll
    for (int j = 0; j < 16; ++j) {
        int dcol = j * 8 + qp * 2;
        float2 r0 = {o_[j][0] * inv0, o_[j][1] * inv0};
        float2 r1 = {o_[j][2] * inv1, o_[j][3] * inv1};
        *reinterpret_cast<float2*>(obase + (size_t)qd * kHD + dcol)       = r0;
        *reinterpret_cast<float2*>(obase + (size_t)(qd + 8) * kHD + dcol) = r1;
    }
}

// ---------------------------------------------------------------------------
// Launch
// ---------------------------------------------------------------------------
extern "C" void kernel_launch(void* const* d_in, const int* in_sizes, int n_in,
                              void* d_out, int out_size) {
    const float* q    = (const float*)d_in[0];
    const float* k    = (const float*)d_in[1];
    const float* v    = (const float*)d_in[2];
    const float* kc   = (const float*)d_in[3];
    const float* vc   = (const float*)d_in[4];
    const int*   slot = (const int*)d_in[5];

    float* out    = (float*)d_out;
    float* out_o  = out;
    float* out_kc = out + (size_t)kN * kHD;
    float* out_vc = out_kc + (size_t)kN * kHKD;

    cudaFuncSetAttribute(attn_kernel,
                         cudaFuncAttributeMaxDynamicSharedMemorySize, SMEM_BYTES);

    int n4 = kN * kHKD / 4;
    cache_copy_kernel<<<(n4 + 255) / 256, 256>>>(kc, vc, out_kc, out_vc);
    scatter_cvt_kernel<<<(n4 + 255) / 256, 256>>>(k, v, slot, out_kc, out_vc);
    dim3 vg(kS / 32, kD / 32, kB * kHK);
    vtrans_kernel<<<vg, dim3(32, 32)>>>(v);

    dim3 grid(NQB, kH, kB);
    attn_kernel<<<grid, NT, SMEM_BYTES>>>(q, out_o);
}

// round 14
// speedup vs baseline: 1.0644x; 1.0424x over previous
#include <cuda_runtime.h>
#include <cuda_bf16.h>
#include <cuda_fp16.h>
#include <cstdint>

// Problem constants
constexpr int kB = 2, kS = 2048, kH = 32, kHK = 8, kD = 128;
constexpr int kN  = kB * kS;      // 4096
constexpr int kHD = kH * kD;      // 4096
constexpr int kHKD = kHK * kD;    // 1024
constexpr float kScale = 0.08838834764831845f;           // 1/sqrt(128)
constexpr float kSc2   = kScale * 1.4426950408889634f;   // scale * log2(e)

// Tiling: BM=128 queries/CTA, BN=64 keys/tile, 4 warps (32 rows each), 2 CTAs/SM
constexpr int BM = 128, BN = 64, NT = 128;
constexpr int NQB = kS / BM;      // 16
constexpr int KP = 136;  // fp16 pitch, conflict-free LDSM (+4 banks/row)
constexpr int VP = 72;

// SMEM element offsets (fp16 elements)
constexpr int eQ  = 0;                    // Q [128][136] fp16 (persistent)
constexpr int eK0 = eQ + BM * KP;         // K buf0 [64][136]
constexpr int eK1 = eK0 + BN * KP;        // K buf1
constexpr int eV  = eK1 + BN * KP;        // V [128][72]
constexpr int SMEM_ELEMS = eV + kD * VP;       // 44032
constexpr int SMEM_BYTES = SMEM_ELEMS * 2;     // 88064 -> 2 CTAs/SM (176128 < 227KB)
static_assert(2 * SMEM_BYTES <= 227328, "smem");

// fp16 scratch: K in source layout; V transposed [bh][d][s]
__device__ __half g_K16[(size_t)kN * kHKD];
__device__ __half g_Vt [(size_t)kN * kHKD];

// ---------------------------------------------------------------------------
// Prep kernels (3 launches)
// ---------------------------------------------------------------------------
__global__ void cache_copy_kernel(const float* __restrict__ kc, const float* __restrict__ vc,
                                  float* __restrict__ okc, float* __restrict__ ovc) {
    int i = blockIdx.x * blockDim.x + threadIdx.x;
    if (i < kN * kHKD / 4) {
        reinterpret_cast<float4*>(okc)[i] = reinterpret_cast<const float4*>(kc)[i];
        reinterpret_cast<float4*>(ovc)[i] = reinterpret_cast<const float4*>(vc)[i];
    }
}
// scatter K/V into caches + convert K to fp16 (k is read once)
__global__ void scatter_cvt_kernel(const float* __restrict__ k, const float* __restrict__ v,
                                   const int* __restrict__ slot,
                                   float* __restrict__ okc, float* __restrict__ ovc) {
    int i = blockIdx.x * blockDim.x + threadIdx.x;
    constexpr int per_row = kHKD / 4;
    if (i >= kN * per_row) return;
    int n = i / per_row, c = i - n * per_row;
    float4 fk = reinterpret_cast<const float4*>(k)[i];
    reinterpret_cast<__half2*>(g_K16)[2 * i]     = __floats2half2_rn(fk.x, fk.y);
    reinterpret_cast<__half2*>(g_K16)[2 * i + 1] = __floats2half2_rn(fk.z, fk.w);
    int s = slot[n];
    if (s >= 0 && s < kN) {
        reinterpret_cast<float4*>(okc)[s * per_row + c] = fk;
        reinterpret_cast<float4*>(ovc)[s * per_row + c] = reinterpret_cast<const float4*>(v)[i];
    }
}
// V -> transposed fp16  Vt[bh][d][s]
__global__ void vtrans_kernel(const float* __restrict__ v) {
    __shared__ __half th[32][33];
    int bh = blockIdx.z;
    int d0 = blockIdx.y * 32, s0 = blockIdx.x * 32;
    int b = bh >> 3, hk = bh & 7;
    int tx = threadIdx.x, ty = threadIdx.y;
    float x = v[((size_t)(b * kS + s0 + ty) * kHK + hk) * kD + d0 + tx];
    th[ty][tx] = __float2half_rn(x);
    __syncthreads();
    g_Vt[((size_t)(bh * kD + d0 + ty)) * kS + s0 + tx] = th[tx][ty];
}

// ---------------------------------------------------------------------------
// PTX helpers
// ---------------------------------------------------------------------------
__device__ __forceinline__ void mma16816(float* d,
                                         unsigned a0, unsigned a1, unsigned a2, unsigned a3,
                                         unsigned b0, unsigned b1) {
    asm volatile(
        "mma.sync.aligned.m16n8k16.row.col.f32.f16.f16.f32 "
        "{%0,%1,%2,%3},{%4,%5,%6,%7},{%8,%9},{%0,%1,%2,%3};\n"
        : "+f"(d[0]), "+f"(d[1]), "+f"(d[2]), "+f"(d[3])
        : "r"(a0), "r"(a1), "r"(a2), "r"(a3), "r"(b0), "r"(b1));
}
__device__ __forceinline__ void ldsm4(unsigned* r, unsigned a) {
    asm volatile("ldmatrix.sync.aligned.m8n8.x4.shared.b16 {%0,%1,%2,%3}, [%4];\n"
                 : "=r"(r[0]), "=r"(r[1]), "=r"(r[2]), "=r"(r[3]) : "r"(a));
}
__device__ __forceinline__ void cp16(unsigned dst, const void* src) {
    asm volatile("cp.async.cg.shared.global [%0], [%1], 16;\n" :: "r"(dst), "l"(src));
}
__device__ __forceinline__ void cp_commit() {
    asm volatile("cp.async.commit_group;" ::: "memory");
}
__device__ __forceinline__ void cp_wait1() {
    asm volatile("cp.async.wait_group 1;" ::: "memory");
}
__device__ __forceinline__ float ex2(float x) {
    float y;
    asm("ex2.approx.f32 %0, %1;" : "=f"(y) : "f"(x));
    return y;
}
__device__ __forceinline__ unsigned pkh2(float x, float y) {
    __half2 t = __floats2half2_rn(x, y);
    return *reinterpret_cast<unsigned*>(&t);
}

// ---------------------------------------------------------------------------
// Flash attention: pure fp16 MMA, warp owns 32 q-rows (m32 amortization),
// static softmax, double-K single-V cp.async pipeline, 2 CTAs/SM.
// Grid (16, 32, 2), 128 threads.
// ---------------------------------------------------------------------------
__global__ __launch_bounds__(NT, 2)
void attn_kernel(const float* __restrict__ q, float* __restrict__ o) {
    extern __shared__ __half sm[];

    const int tid = threadIdx.x;
    const int w = tid >> 5;
    const int lane = tid & 31;
    const int qd = lane >> 2;   // 0..7
    const int qp = lane & 3;    // 0..3
    const int qb = (NQB - 1) - blockIdx.x;   // heavy CTAs first
    const int h = blockIdx.y, b = blockIdx.z;
    const int hk = h >> 2;
    const int bh = b * kHK + hk;
    const int nk = 2 * (qb + 1);

    const uint32_t sb = (uint32_t)__cvta_generic_to_shared(sm);

    // B-operand ldsm mapping (K, V): lanes 0-7 -> n0-7/k0 ; 8-15 -> n0-7/k8 ;
    //                                16-23 -> n8-15/k0 ; 24-31 -> n8-15/k8
    const int lrB = ((lane >> 4) << 3) + (lane & 7);
    const int lcB = ((lane >> 3) & 1) << 3;
    // A-operand ldsm mapping (Q): lanes 0-7 -> r0-7/k0 ; 8-15 -> r8-15/k0 ;
    //                             16-23 -> r0-7/k8 ; 24-31 -> r8-15/k8
    const int lrA = (lane & 7) + (((lane >> 3) & 1) << 3);
    const int lcA = (lane >> 4) << 3;

    const unsigned uQ[2] = {
        sb + (unsigned)((eQ + (32 * w +  0 + lrA) * KP + lcA) * 2),
        sb + (unsigned)((eQ + (32 * w + 16 + lrA) * KP + lcA) * 2)};
    const unsigned uK[2] = {
        sb + (unsigned)((eK0 + lrB * KP + lcB) * 2),
        sb + (unsigned)((eK1 + lrB * KP + lcB) * 2)};
    const unsigned uV = sb + (unsigned)((eV + lrB * VP + lcB) * 2);

    const __half* gK0 = g_K16 + ((size_t)(b * kS)) * kHKD + hk * kD;
    const __half* gV0 = g_Vt + (size_t)bh * kD * kS;

    auto prefetchK = [&](int kt) {
        unsigned dK = sb + (unsigned)(((kt & 1) ? eK1 : eK0) * 2);
        const __half* kp = gK0 + (size_t)kt * BN * kHKD;
        #pragma unroll
        for (int it = 0; it < 8; ++it) {
            int idx = it * NT + tid;            // 0..1023
            int r = idx >> 4, c = (idx & 15) * 8;
            cp16(dK + (unsigned)((r * KP + c) * 2), kp + (size_t)r * kHKD + c);
        }
        cp_commit();
    };
    auto prefetchV = [&](int kt) {
        const __half* vp = gV0 + (size_t)kt * BN;
        #pragma unroll
        for (int it = 0; it < 8; ++it) {
            int idx = it * NT + tid;            // 0..1023
            int r = idx >> 3, c = (idx & 7) * 8;
            cp16(sb + (unsigned)(eV * 2) + (unsigned)((r * VP + c) * 2),
                 vp + (size_t)r * kS + c);
        }
        cp_commit();
    };

    prefetchK(0);    // group: K(0)
    prefetchV(0);    // group: V(0)

    // ---- Q: load fp32, pre-scale, convert fp16 into persistent smem tile ----
    const float* qbase = q + ((size_t)(b * kS + qb * BM)) * kHD + h * kD;
    #pragma unroll
    for (int it = 0; it < 32; ++it) {
        int idx = it * NT + tid;               // 0..4095 float4s (128 rows x 32)
        int r = idx >> 5, c = (idx & 31) * 4;
        float4 f = *reinterpret_cast<const float4*>(qbase + (size_t)r * kHD + c);
        f.x *= kSc2; f.y *= kSc2; f.z *= kSc2; f.w *= kSc2;
        unsigned h0 = pkh2(f.x, f.y), h1 = pkh2(f.z, f.w);
        *reinterpret_cast<unsigned*>(&sm[eQ + r * KP + c])     = h0;
        *reinterpret_cast<unsigned*>(&sm[eQ + r * KP + c + 2]) = h1;
    }
    __syncthreads();

    float o_[2][16][4];
    #pragma unroll
    for (int mb = 0; mb < 2; ++mb)
        #pragma unroll
        for (int j = 0; j < 16; ++j)
            #pragma unroll
            for (int e = 0; e < 4; ++e) o_[mb][j][e] = 0.f;
    float lr[2][2] = {{0.f, 0.f}, {0.f, 0.f}};

    const int rgq = qb * BM + 32 * w + qd;  // row of (mb=0, half 0)

    for (int kt = 0; kt < nk; ++kt) {
        const int bw = kt & 1;

        // K(kt) ready (allow V(kt) pending)
        cp_wait1();
        __syncthreads();

        // ---- S = Q16 . K16 ; warp computes m32 x n64 ----
        float s_[2][8][4];
        #pragma unroll
        for (int mb = 0; mb < 2; ++mb)
            #pragma unroll
            for (int j = 0; j < 8; ++j)
                #pragma unroll
                for (int e = 0; e < 4; ++e) s_[mb][j][e] = 0.f;

        #pragma unroll
        for (int c = 0; c < 8; ++c) {
            unsigned qf[2][4];
            ldsm4(qf[0], uQ[0] + (unsigned)(c * 32));
            ldsm4(qf[1], uQ[1] + (unsigned)(c * 32));
            #pragma unroll
            for (int nb = 0; nb < 4; ++nb) {
                unsigned f[4];
                ldsm4(f, uK[bw] + (unsigned)((nb * 16 * KP + c * 16) * 2));
                mma16816(s_[0][2 * nb],     qf[0][0], qf[0][1], qf[0][2], qf[0][3], f[0], f[1]);
                mma16816(s_[0][2 * nb + 1], qf[0][0], qf[0][1], qf[0][2], qf[0][3], f[2], f[3]);
                mma16816(s_[1][2 * nb],     qf[1][0], qf[1][1], qf[1][2], qf[1][3], f[0], f[1]);
                mma16816(s_[1][2 * nb + 1], qf[1][0], qf[1][1], qf[1][2], qf[1][3], f[2], f[3]);
            }
        }
        __syncthreads();               // all warps done reading K(kt)
        if (kt + 1 < nk) prefetchK(kt + 1);   // into other K buf

        // ---- static softmax: p = 2^s, pack to fp16 immediately ----
        const bool msk = (kt >= 2 * qb);
        unsigned pp[2][8][2];
        #pragma unroll
        for (int mb = 0; mb < 2; ++mb) {
            const int rg0 = rgq + 16 * mb;
            const int rg1 = rg0 + 8;
            #pragma unroll
            for (int j = 0; j < 8; ++j) {
                int cl = kt * BN + j * 8 + qp * 2;
                float p0 = ex2(s_[mb][j][0]);
                float p1 = ex2(s_[mb][j][1]);
                float p2 = ex2(s_[mb][j][2]);
                float p3 = ex2(s_[mb][j][3]);
                if (msk) {
                    if (cl     > rg0) p0 = 0.f;
                    if (cl + 1 > rg0) p1 = 0.f;
                    if (cl     > rg1) p2 = 0.f;
                    if (cl + 1 > rg1) p3 = 0.f;
                }
                lr[mb][0] += p0 + p1;
                lr[mb][1] += p2 + p3;
                pp[mb][j][0] = pkh2(p0, p1);
                pp[mb][j][1] = pkh2(p2, p3);
            }
        }

        // V(kt) ready (allow K(kt+1) pending)
        cp_wait1();
        __syncthreads();

        // ---- O += P16 . V16 ; each V-frag feeds 4 MMAs ----
        #pragma unroll
        for (int cc = 0; cc < 4; ++cc) {
            #pragma unroll
            for (int db = 0; db < 8; ++db) {
                unsigned f[4];
                ldsm4(f, uV + (unsigned)((db * 16 * VP + cc * 16) * 2));
                mma16816(o_[0][2 * db],     pp[0][2 * cc][0], pp[0][2 * cc][1],
                         pp[0][2 * cc + 1][0], pp[0][2 * cc + 1][1], f[0], f[1]);
                mma16816(o_[0][2 * db + 1], pp[0][2 * cc][0], pp[0][2 * cc][1],
                         pp[0][2 * cc + 1][0], pp[0][2 * cc + 1][1], f[2], f[3]);
                mma16816(o_[1][2 * db],     pp[1][2 * cc][0], pp[1][2 * cc][1],
                         pp[1][2 * cc + 1][0], pp[1][2 * cc + 1][1], f[0], f[1]);
                mma16816(o_[1][2 * db + 1], pp[1][2 * cc][0], pp[1][2 * cc][1],
                         pp[1][2 * cc + 1][0], pp[1][2 * cc + 1][1], f[2], f[3]);
            }
        }
        __syncthreads();               // all warps done reading V(kt)
        if (kt + 1 < nk) prefetchV(kt + 1);
    }

    // ---- final l reduce over qp lanes, normalize, store ----
    #pragma unroll
    for (int mb = 0; mb < 2; ++mb)
        #pragma unroll
        for (int hh = 0; hh < 2; ++hh) {
            lr[mb][hh] += __shfl_xor_sync(0xffffffffu, lr[mb][hh], 1);
            lr[mb][hh] += __shfl_xor_sync(0xffffffffu, lr[mb][hh], 2);
        }
    float* obase = o + ((size_t)(b * kS + qb * BM + 32 * w)) * kHD + h * kD;
    #pragma unroll
    for (int mb = 0; mb < 2; ++mb) {
        float inv0 = 1.0f / lr[mb][0], inv1 = 1.0f / lr[mb][1];
        #pragma unroll
        for (int j = 0; j < 16; ++j) {
            int dcol = j * 8 + qp * 2;
            float2 r0 = {o_[mb][j][0] * inv0, o_[mb][j][1] * inv0};
            float2 r1 = {o_[mb][j][2] * inv1, o_[mb][j][3] * inv1};
            *reinterpret_cast<float2*>(obase + (size_t)(16 * mb + qd) * kHD + dcol)     = r0;
            *reinterpret_cast<float2*>(obase + (size_t)(16 * mb + qd + 8) * kHD + dcol) = r1;
        }
    }
}

// ---------------------------------------------------------------------------
// Launch
// ---------------------------------------------------------------------------
extern "C" void kernel_launch(void* const* d_in, const int* in_sizes, int n_in,
                              void* d_out, int out_size) {
    const float* q    = (const float*)d_in[0];
    const float* k    = (const float*)d_in[1];
    const float* v    = (const float*)d_in[2];
    const float* kc   = (const float*)d_in[3];
    const float* vc   = (const float*)d_in[4];
    const int*   slot = (const int*)d_in[5];

    float* out    = (float*)d_out;
    float* out_o  = out;
    float* out_kc = out + (size_t)kN * kHD;
    float* out_vc = out_kc + (size_t)kN * kHKD;

    cudaFuncSetAttribute(attn_kernel,
                         cudaFuncAttributeMaxDynamicSharedMemorySize, SMEM_BYTES);

    int n4 = kN * kHKD / 4;
    cache_copy_kernel<<<(n4 + 255) / 256, 256>>>(kc, vc, out_kc, out_vc);
    scatter_cvt_kernel<<<(n4 + 255) / 256, 256>>>(k, v, slot, out_kc, out_vc);
    dim3 vg(kS / 32, kD / 32, kB * kHK);
    vtrans_kernel<<<vg, dim3(32, 32)>>>(v);

    dim3 grid(NQB, kH, kB);
    attn_kernel<<<grid, NT, SMEM_BYTES>>>(q, out_o);
}

// round 16
// speedup vs baseline: 1.1085x; 1.0414x over previous
#include <cuda_runtime.h>
#include <cuda_bf16.h>
#include <cuda_fp16.h>
#include <cstdint>

// Problem constants
constexpr int kB = 2, kS = 2048, kH = 32, kHK = 8, kD = 128;
constexpr int kN  = kB * kS;      // 4096
constexpr int kHD = kH * kD;      // 4096
constexpr int kHKD = kHK * kD;    // 1024
constexpr float kScale = 0.08838834764831845f;           // 1/sqrt(128)
constexpr float kSc2   = kScale * 1.4426950408889634f;   // scale * log2(e)

// Tiling: BM=128 queries/CTA, BN=64 keys/tile, 4 warps (32 rows each), 2 CTAs/SM
constexpr int BM = 128, BN = 64, NT = 128;
constexpr int NQB = kS / BM;      // 16
constexpr int KP = 136;  // fp16 pitch, conflict-free LDSM (+4 banks/row)
constexpr int VP = 72;

// SMEM element offsets (fp16 elements)
constexpr int eQ  = 0;                    // Q [128][136] fp16 (persistent)
constexpr int eK0 = eQ + BM * KP;         // K buf0 [64][136]
constexpr int eK1 = eK0 + BN * KP;        // K buf1
constexpr int eV  = eK1 + BN * KP;        // V [128][72]
constexpr int SMEM_ELEMS = eV + kD * VP;       // 44032
constexpr int SMEM_BYTES = SMEM_ELEMS * 2;     // 88064 -> 2 CTAs/SM
static_assert(2 * SMEM_BYTES <= 227328, "smem");

// fp16 scratch: K in source layout; V transposed [bh][d][s]
__device__ __half g_K16[(size_t)kN * kHKD];
__device__ __half g_Vt [(size_t)kN * kHKD];

// ---------------------------------------------------------------------------
// Prep kernels (3 launches)
// ---------------------------------------------------------------------------
__global__ void cache_copy_kernel(const float* __restrict__ kc, const float* __restrict__ vc,
                                  float* __restrict__ okc, float* __restrict__ ovc) {
    int i = blockIdx.x * blockDim.x + threadIdx.x;
    if (i < kN * kHKD / 4) {
        reinterpret_cast<float4*>(okc)[i] = reinterpret_cast<const float4*>(kc)[i];
        reinterpret_cast<float4*>(ovc)[i] = reinterpret_cast<const float4*>(vc)[i];
    }
}
__global__ void scatter_cvt_kernel(const float* __restrict__ k, const float* __restrict__ v,
                                   const int* __restrict__ slot,
                                   float* __restrict__ okc, float* __restrict__ ovc) {
    int i = blockIdx.x * blockDim.x + threadIdx.x;
    constexpr int per_row = kHKD / 4;
    if (i >= kN * per_row) return;
    int n = i / per_row, c = i - n * per_row;
    float4 fk = reinterpret_cast<const float4*>(k)[i];
    reinterpret_cast<__half2*>(g_K16)[2 * i]     = __floats2half2_rn(fk.x, fk.y);
    reinterpret_cast<__half2*>(g_K16)[2 * i + 1] = __floats2half2_rn(fk.z, fk.w);
    int s = slot[n];
    if (s >= 0 && s < kN) {
        reinterpret_cast<float4*>(okc)[s * per_row + c] = fk;
        reinterpret_cast<float4*>(ovc)[s * per_row + c] = reinterpret_cast<const float4*>(v)[i];
    }
}
__global__ void vtrans_kernel(const float* __restrict__ v) {
    __shared__ __half th[32][33];
    int bh = blockIdx.z;
    int d0 = blockIdx.y * 32, s0 = blockIdx.x * 32;
    int b = bh >> 3, hk = bh & 7;
    int tx = threadIdx.x, ty = threadIdx.y;
    float x = v[((size_t)(b * kS + s0 + ty) * kHK + hk) * kD + d0 + tx];
    th[ty][tx] = __float2half_rn(x);
    __syncthreads();
    g_Vt[((size_t)(bh * kD + d0 + ty)) * kS + s0 + tx] = th[tx][ty];
}

// ---------------------------------------------------------------------------
// PTX helpers
// ---------------------------------------------------------------------------
__device__ __forceinline__ void mma16816(float* d,
                                         unsigned a0, unsigned a1, unsigned a2, unsigned a3,
                                         unsigned b0, unsigned b1) {
    asm volatile(
        "mma.sync.aligned.m16n8k16.row.col.f32.f16.f16.f32 "
        "{%0,%1,%2,%3},{%4,%5,%6,%7},{%8,%9},{%0,%1,%2,%3};\n"
        : "+f"(d[0]), "+f"(d[1]), "+f"(d[2]), "+f"(d[3])
        : "r"(a0), "r"(a1), "r"(a2), "r"(a3), "r"(b0), "r"(b1));
}
// fp16-accumulator variant: D/C are 2x f16x2 regs
__device__ __forceinline__ void mma16816h(unsigned* d,
                                          unsigned a0, unsigned a1, unsigned a2, unsigned a3,
                                          unsigned b0, unsigned b1) {
    asm volatile(
        "mma.sync.aligned.m16n8k16.row.col.f16.f16.f16.f16 "
        "{%0,%1},{%2,%3,%4,%5},{%6,%7},{%0,%1};\n"
        : "+r"(d[0]), "+r"(d[1])
        : "r"(a0), "r"(a1), "r"(a2), "r"(a3), "r"(b0), "r"(b1));
}
__device__ __forceinline__ void ldsm4(unsigned* r, unsigned a) {
    asm volatile("ldmatrix.sync.aligned.m8n8.x4.shared.b16 {%0,%1,%2,%3}, [%4];\n"
                 : "=r"(r[0]), "=r"(r[1]), "=r"(r[2]), "=r"(r[3]) : "r"(a));
}
__device__ __forceinline__ void cp16(unsigned dst, const void* src) {
    asm volatile("cp.async.cg.shared.global [%0], [%1], 16;\n" :: "r"(dst), "l"(src));
}
__device__ __forceinline__ void cp_commit() {
    asm volatile("cp.async.commit_group;" ::: "memory");
}
__device__ __forceinline__ void cp_wait1() {
    asm volatile("cp.async.wait_group 1;" ::: "memory");
}
__device__ __forceinline__ unsigned h2ex2(unsigned x) {
    unsigned y;
    asm("ex2.approx.f16x2 %0, %1;" : "=r"(y) : "r"(x));
    return y;
}
__device__ __forceinline__ unsigned hadd2u(unsigned a, unsigned b) {
    unsigned r;
    asm("add.f16x2 %0, %1, %2;" : "=r"(r) : "r"(a), "r"(b));
    return r;
}
__device__ __forceinline__ unsigned hmul2u(unsigned a, unsigned b) {
    unsigned r;
    asm("mul.f16x2 %0, %1, %2;" : "=r"(r) : "r"(a), "r"(b));
    return r;
}
__device__ __forceinline__ float h2sumf(unsigned a) {
    __half2 h = *reinterpret_cast<__half2*>(&a);
    return __low2float(h) + __high2float(h);
}
__device__ __forceinline__ unsigned pkh2(float x, float y) {
    __half2 t = __floats2half2_rn(x, y);
    return *reinterpret_cast<unsigned*>(&t);
}

// ---------------------------------------------------------------------------
// Flash attention: fp16 MMA with fp16 S-accumulator, f16x2 softmax (ex2.h2),
// warp owns 32 q-rows, double-K single-V cp.async pipeline, 2 CTAs/SM.
// Grid (16, 32, 2), 128 threads.
// ---------------------------------------------------------------------------
__global__ __launch_bounds__(NT, 2)
void attn_kernel(const float* __restrict__ q, float* __restrict__ o) {
    extern __shared__ __half sm[];

    const int tid = threadIdx.x;
    const int w = tid >> 5;
    const int lane = tid & 31;
    const int qd = lane >> 2;   // 0..7
    const int qp = lane & 3;    // 0..3
    const int qb = (NQB - 1) - blockIdx.x;   // heavy CTAs first
    const int h = blockIdx.y, b = blockIdx.z;
    const int hk = h >> 2;
    const int bh = b * kHK + hk;
    const int nk = 2 * (qb + 1);

    const uint32_t sb = (uint32_t)__cvta_generic_to_shared(sm);

    // B-operand ldsm mapping (K, V)
    const int lrB = ((lane >> 4) << 3) + (lane & 7);
    const int lcB = ((lane >> 3) & 1) << 3;
    // A-operand ldsm mapping (Q)
    const int lrA = (lane & 7) + (((lane >> 3) & 1) << 3);
    const int lcA = (lane >> 4) << 3;

    const unsigned uQ[2] = {
        sb + (unsigned)((eQ + (32 * w +  0 + lrA) * KP + lcA) * 2),
        sb + (unsigned)((eQ + (32 * w + 16 + lrA) * KP + lcA) * 2)};
    const unsigned uK[2] = {
        sb + (unsigned)((eK0 + lrB * KP + lcB) * 2),
        sb + (unsigned)((eK1 + lrB * KP + lcB) * 2)};
    const unsigned uV = sb + (unsigned)((eV + lrB * VP + lcB) * 2);

    const __half* gK0 = g_K16 + ((size_t)(b * kS)) * kHKD + hk * kD;
    const __half* gV0 = g_Vt + (size_t)bh * kD * kS;

    auto prefetchK = [&](int kt) {
        unsigned dK = sb + (unsigned)(((kt & 1) ? eK1 : eK0) * 2);
        const __half* kp = gK0 + (size_t)kt * BN * kHKD;
        #pragma unroll
        for (int it = 0; it < 8; ++it) {
            int idx = it * NT + tid;            // 0..1023
            int r = idx >> 4, c = (idx & 15) * 8;
            cp16(dK + (unsigned)((r * KP + c) * 2), kp + (size_t)r * kHKD + c);
        }
        cp_commit();
    };
    auto prefetchV = [&](int kt) {
        const __half* vp = gV0 + (size_t)kt * BN;
        #pragma unroll
        for (int it = 0; it < 8; ++it) {
            int idx = it * NT + tid;            // 0..1023
            int r = idx >> 3, c = (idx & 7) * 8;
            cp16(sb + (unsigned)(eV * 2) + (unsigned)((r * VP + c) * 2),
                 vp + (size_t)r * kS + c);
        }
        cp_commit();
    };

    prefetchK(0);    // group: K(0)
    prefetchV(0);    // group: V(0)

    // ---- Q: load fp32, pre-scale, convert fp16 into persistent smem tile ----
    const float* qbase = q + ((size_t)(b * kS + qb * BM)) * kHD + h * kD;
    #pragma unroll
    for (int it = 0; it < 32; ++it) {
        int idx = it * NT + tid;               // 0..4095 float4s
        int r = idx >> 5, c = (idx & 31) * 4;
        float4 f = *reinterpret_cast<const float4*>(qbase + (size_t)r * kHD + c);
        f.x *= kSc2; f.y *= kSc2; f.z *= kSc2; f.w *= kSc2;
        unsigned h0 = pkh2(f.x, f.y), h1 = pkh2(f.z, f.w);
        *reinterpret_cast<unsigned*>(&sm[eQ + r * KP + c])     = h0;
        *reinterpret_cast<unsigned*>(&sm[eQ + r * KP + c + 2]) = h1;
    }
    __syncthreads();

    float o_[2][16][4];
    #pragma unroll
    for (int mb = 0; mb < 2; ++mb)
        #pragma unroll
        for (int j = 0; j < 16; ++j)
            #pragma unroll
            for (int e = 0; e < 4; ++e) o_[mb][j][e] = 0.f;
    float lr[2][2] = {{0.f, 0.f}, {0.f, 0.f}};

    const int rgq = qb * BM + 32 * w + qd;  // row of (mb=0, half 0)

    for (int kt = 0; kt < nk; ++kt) {
        const int bw = kt & 1;

        // K(kt) ready (allow V(kt) pending)
        cp_wait1();
        __syncthreads();

        // ---- S = Q16 . K16 (fp16 accumulator, packed f16x2 output) ----
        unsigned s_[2][8][2];
        #pragma unroll
        for (int mb = 0; mb < 2; ++mb)
            #pragma unroll
            for (int j = 0; j < 8; ++j) { s_[mb][j][0] = 0u; s_[mb][j][1] = 0u; }

        #pragma unroll
        for (int c = 0; c < 8; ++c) {
            unsigned qf[2][4];
            ldsm4(qf[0], uQ[0] + (unsigned)(c * 32));
            ldsm4(qf[1], uQ[1] + (unsigned)(c * 32));
            #pragma unroll
            for (int nb = 0; nb < 4; ++nb) {
                unsigned f[4];
                ldsm4(f, uK[bw] + (unsigned)((nb * 16 * KP + c * 16) * 2));
                mma16816h(s_[0][2 * nb],     qf[0][0], qf[0][1], qf[0][2], qf[0][3], f[0], f[1]);
                mma16816h(s_[0][2 * nb + 1], qf[0][0], qf[0][1], qf[0][2], qf[0][3], f[2], f[3]);
                mma16816h(s_[1][2 * nb],     qf[1][0], qf[1][1], qf[1][2], qf[1][3], f[0], f[1]);
                mma16816h(s_[1][2 * nb + 1], qf[1][0], qf[1][1], qf[1][2], qf[1][3], f[2], f[3]);
            }
        }
        __syncthreads();               // all warps done reading K(kt)
        if (kt + 1 < nk) prefetchK(kt + 1);

        // ---- softmax in f16x2: p = 2^s, mask via {0,1} mul, l via HADD2 ----
        const bool msk = (kt >= 2 * qb);
        unsigned accH[2][2] = {{0u, 0u}, {0u, 0u}};
        #pragma unroll
        for (int mb = 0; mb < 2; ++mb) {
            const int r0 = rgq + 16 * mb;
            const int r1 = r0 + 8;
            #pragma unroll
            for (int j = 0; j < 8; ++j) {
                unsigned x0 = h2ex2(s_[mb][j][0]);
                unsigned x1 = h2ex2(s_[mb][j][1]);
                if (msk) {
                    int cl = kt * BN + j * 8 + qp * 2;
                    unsigned m0 = (cl <= r0 ? 0x3C00u : 0u) | (cl + 1 <= r0 ? 0x3C000000u : 0u);
                    unsigned m1 = (cl <= r1 ? 0x3C00u : 0u) | (cl + 1 <= r1 ? 0x3C000000u : 0u);
                    x0 = hmul2u(x0, m0);
                    x1 = hmul2u(x1, m1);
                }
                accH[mb][0] = hadd2u(accH[mb][0], x0);
                accH[mb][1] = hadd2u(accH[mb][1], x1);
                s_[mb][j][0] = x0;
                s_[mb][j][1] = x1;
            }
        }
        #pragma unroll
        for (int mb = 0; mb < 2; ++mb) {
            lr[mb][0] += h2sumf(accH[mb][0]);
            lr[mb][1] += h2sumf(accH[mb][1]);
        }

        // V(kt) ready (allow K(kt+1) pending)
        cp_wait1();
        __syncthreads();

        // ---- O += P16 . V16 (P already packed in A-fragment layout) ----
        #pragma unroll
        for (int cc = 0; cc < 4; ++cc) {
            #pragma unroll
            for (int db = 0; db < 8; ++db) {
                unsigned f[4];
                ldsm4(f, uV + (unsigned)((db * 16 * VP + cc * 16) * 2));
                mma16816(o_[0][2 * db],     s_[0][2 * cc][0], s_[0][2 * cc][1],
                         s_[0][2 * cc + 1][0], s_[0][2 * cc + 1][1], f[0], f[1]);
                mma16816(o_[0][2 * db + 1], s_[0][2 * cc][0], s_[0][2 * cc][1],
                         s_[0][2 * cc + 1][0], s_[0][2 * cc + 1][1], f[2], f[3]);
                mma16816(o_[1][2 * db],     s_[1][2 * cc][0], s_[1][2 * cc][1],
                         s_[1][2 * cc + 1][0], s_[1][2 * cc + 1][1], f[0], f[1]);
                mma16816(o_[1][2 * db + 1], s_[1][2 * cc][0], s_[1][2 * cc][1],
                         s_[1][2 * cc + 1][0], s_[1][2 * cc + 1][1], f[2], f[3]);
            }
        }
        __syncthreads();               // all warps done reading V(kt)
        if (kt + 1 < nk) prefetchV(kt + 1);
    }

    // ---- final l reduce over qp lanes, normalize, store ----
    #pragma unroll
    for (int mb = 0; mb < 2; ++mb)
        #pragma unroll
        for (int hh = 0; hh < 2; ++hh) {
            lr[mb][hh] += __shfl_xor_sync(0xffffffffu, lr[mb][hh], 1);
            lr[mb][hh] += __shfl_xor_sync(0xffffffffu, lr[mb][hh], 2);
        }
    float* obase = o + ((size_t)(b * kS + qb * BM + 32 * w)) * kHD + h * kD;
    #pragma unroll
    for (int mb = 0; mb < 2; ++mb) {
        float inv0 = 1.0f / lr[mb][0], inv1 = 1.0f / lr[mb][1];
        #pragma unroll
        for (int j = 0; j < 16; ++j) {
            int dcol = j * 8 + qp * 2;
            float2 r0 = {o_[mb][j][0] * inv0, o_[mb][j][1] * inv0};
            float2 r1 = {o_[mb][j][2] * inv1, o_[mb][j][3] * inv1};
            *reinterpret_cast<float2*>(obase + (size_t)(16 * mb + qd) * kHD + dcol)     = r0;
            *reinterpret_cast<float2*>(obase + (size_t)(16 * mb + qd + 8) * kHD + dcol) = r1;
        }
    }
}

// ---------------------------------------------------------------------------
// Launch
// ---------------------------------------------------------------------------
extern "C" void kernel_launch(void* const* d_in, const int* in_sizes, int n_in,
                              void* d_out, int out_size) {
    const float* q    = (const float*)d_in[0];
    const float* k    = (const float*)d_in[1];
    const float* v    = (const float*)d_in[2];
    const float* kc   = (const float*)d_in[3];
    const float* vc   = (const float*)d_in[4];
    const int*   slot = (const int*)d_in[5];

    float* out    = (float*)d_out;
    float* out_o  = out;
    float* out_kc = out + (size_t)kN * kHD;
    float* out_vc = out_kc + (size_t)kN * kHKD;

    cudaFuncSetAttribute(attn_kernel,
                         cudaFuncAttributeMaxDynamicSharedMemorySize, SMEM_BYTES);

    int n4 = kN * kHKD / 4;
    cache_copy_kernel<<<(n4 + 255) / 256, 256>>>(kc, vc, out_kc, out_vc);
    scatter_cvt_kernel<<<(n4 + 255) / 256, 256>>>(k, v, slot, out_kc, out_vc);
    dim3 vg(kS / 32, kD / 32, kB * kHK);
    vtrans_kernel<<<vg, dim3(32, 32)>>>(v);

    dim3 grid(NQB, kH, kB);
    attn_kernel<<<grid, NT, SMEM_BYTES>>>(q, out_o);
}